// round 12
// baseline (speedup 1.0000x reference)
#include <cuda_runtime.h>
#include <math.h>
#include <stdint.h>

#define TT    1024
#define DD    2048
#define DFF   1024
#define EE    16
#define KSLOT 6
#define TK    (TT*KSLOT)
#define MAXTILES 64
#define KT    32
#define LDSW  40   // smem row stride (words); conflict-free for float2 frags

// ---------------- scratch (device globals; no allocations allowed) ----------
__device__ int   g_off[EE + 1];
__device__ int   g_tok[TK];
__device__ int   g_slot[TK];
__device__ float g_wt[TK];
__device__ int   g_tile_e[MAXTILES];
__device__ int   g_tile_m0[MAXTILES];
__device__ int   g_ntiles;
__device__ __align__(16) float g_X[(size_t)TT * DD];            // tf32-rounded x
__device__ __align__(16) float g_H[(size_t)(TK + 128) * DFF];   // tf32-rounded h
__device__ __align__(16) float g_Y[(size_t)TK * DD];

// ---------------- helpers ----------------------------------------------------
__device__ __forceinline__ uint32_t f2tf(float f) {
    uint32_t u;
    asm("cvt.rna.tf32.f32 %0, %1;" : "=r"(u) : "f"(f));
    return u;
}
__device__ __forceinline__ uint4 tf4(float4 v) {
    return make_uint4(f2tf(v.x), f2tf(v.y), f2tf(v.z), f2tf(v.w));
}

__device__ __forceinline__ void mma_tf32(float& d0, float& d1, float& d2, float& d3,
                                         uint32_t a0, uint32_t a1, uint32_t a2, uint32_t a3,
                                         uint32_t b0, uint32_t b1) {
    asm volatile(
        "mma.sync.aligned.m16n8k8.row.col.f32.tf32.tf32.f32 "
        "{%0,%1,%2,%3},{%4,%5,%6,%7},{%8,%9},{%0,%1,%2,%3};"
        : "+f"(d0), "+f"(d1), "+f"(d2), "+f"(d3)
        : "r"(a0), "r"(a1), "r"(a2), "r"(a3), "r"(b0), "r"(b1));
}

__device__ __forceinline__ void cp16(void* smem_dst, const void* gmem_src) {
    unsigned d = (unsigned)__cvta_generic_to_shared(smem_dst);
    asm volatile("cp.async.cg.shared.global [%0], [%1], 16;" :: "r"(d), "l"(gmem_src));
}
#define CP_COMMIT() asm volatile("cp.async.commit_group;")
#define CP_WAIT1()  asm volatile("cp.async.wait_group 1;")

// ---------------- prep: g_X = rna_tf32(x) -----------------------------------
__global__ void k_prep(const float* __restrict__ x) {
    int i = (blockIdx.x * blockDim.x + threadIdx.x) * 4;
    float4 v = *reinterpret_cast<const float4*>(x + i);
    *reinterpret_cast<uint4*>(g_X + i) = tf4(v);
}

// ---------------- routing: one CTA does count+scan+scatter ------------------
__global__ void k_route(const int* __restrict__ se, const float* __restrict__ rw) {
    __shared__ int cnt[EE], cur[EE], off[EE + 1];
    int tid = threadIdx.x;
    if (tid < EE) { cnt[tid] = 0; cur[tid] = 0; }
    __syncthreads();
    for (int i = tid; i < TK; i += 1024) atomicAdd(&cnt[se[i] & (EE - 1)], 1);
    __syncthreads();
    if (tid == 0) {
        int s = 0, nt = 0;
        off[0] = 0; g_off[0] = 0;
        for (int e = 0; e < EE; e++) {
            int o = s;
            s += cnt[e];
            off[e + 1] = s; g_off[e + 1] = s;
            for (int m0 = o; m0 < s; m0 += 128) {
                g_tile_e[nt] = e; g_tile_m0[nt] = m0; nt++;
            }
        }
        g_ntiles = nt;
    }
    __syncthreads();
    for (int i = tid; i < TK; i += 1024) {
        int e = se[i] & (EE - 1);
        int p = off[e] + atomicAdd(&cur[e], 1);
        g_tok[p]  = i / KSLOT;
        g_slot[p] = i;
        g_wt[p]   = rw[i];
    }
}

// ---------------- pass 1: H = silu(x@w0^T*s0) * (x@w1^T*s1) -----------------
// Block: 128(M) x 32(N dff), gate+up. 8 warps = 2(M) x 4(N); warp 64x8 per mat.
// 32 accs/thread -> occupancy 3. Buffer rows: A 0-127, Bg 128-159, Bu 160-191.
#define P1_ROWS 192
#define P1_SMEM (2*P1_ROWS*LDSW*4 + 512)

__global__ __launch_bounds__(256, 3)
void k_gateup(const float* __restrict__ w0,
              const float* __restrict__ w1,
              const float* __restrict__ s0,
              const float* __restrict__ s1) {
    int tile = blockIdx.x;
    if (tile >= g_ntiles) return;
    int e   = g_tile_e[tile];
    int m0  = g_tile_m0[tile];
    int end = g_off[e + 1];
    int n0  = blockIdx.y * 32;

    extern __shared__ __align__(16) float sm[];
    float (*buf)[P1_ROWS * LDSW] = (float(*)[P1_ROWS * LDSW])sm;
    int* toks = (int*)(sm + 2 * P1_ROWS * LDSW);

    int tid = threadIdx.x;
    if (tid < 128) {
        int m = m0 + tid;
        toks[tid] = (m < end) ? g_tok[m] : 0;
    }
    __syncthreads();

    const float* w0e = w0 + (size_t)e * DFF * DD;
    const float* w1e = w1 + (size_t)e * DFF * DD;

    auto prefetch = [&](int s, int k0) {
        float* b = buf[s];
#pragma unroll
        for (int i = 0; i < 4; i++) {
            int lin = tid + i * 256, row = lin >> 3, c4 = (lin & 7) * 4;
            cp16(b + row * LDSW + c4, g_X + (size_t)toks[row] * DD + k0 + c4);
        }
        {
            int row = tid >> 3, c4 = (tid & 7) * 4;      // 32 rows x 8 f4
            size_t boff = (size_t)(n0 + row) * DD + k0 + c4;
            cp16(b + (128 + row) * LDSW + c4, w0e + boff);
            cp16(b + (160 + row) * LDSW + c4, w1e + boff);
        }
    };

    int w  = tid >> 5, L = tid & 31;
    int wm = w & 1, wn = w >> 1;       // 2(M) x 4(N)
    int rm = wm * 64, cn = wn * 8;
    int cw = 2 * (L & 3);              // column-pair base within kk group

    float accg[4][4] = {}, accu[4][4] = {};

    const int NT = DD / KT;   // 64
    prefetch(0, 0);
    CP_COMMIT();

    for (int it = 0; it < NT; it++) {
        if (it + 1 < NT) prefetch((it + 1) & 1, (it + 1) * KT);
        CP_COMMIT();
        CP_WAIT1();
        __syncthreads();
        const float* bp = buf[it & 1];

#pragma unroll
        for (int kk = 0; kk < KT; kk += 8) {
            uint32_t a[4][4];
#pragma unroll
            for (int mt = 0; mt < 4; mt++) {
                int r = rm + mt * 16 + (L >> 2);
                float2 lo = *reinterpret_cast<const float2*>(bp + r * LDSW + kk + cw);
                float2 hi = *reinterpret_cast<const float2*>(bp + (r + 8) * LDSW + kk + cw);
                a[mt][0] = __float_as_uint(lo.x);
                a[mt][1] = __float_as_uint(hi.x);
                a[mt][2] = __float_as_uint(lo.y);
                a[mt][3] = __float_as_uint(hi.y);
            }
            {
                int col = cn + (L >> 2);
                float2 gg = *reinterpret_cast<const float2*>(bp + (128 + col) * LDSW + kk + cw);
                float2 uu = *reinterpret_cast<const float2*>(bp + (160 + col) * LDSW + kk + cw);
                uint32_t bg0 = f2tf(gg.x), bg1 = f2tf(gg.y);
                uint32_t bu0 = f2tf(uu.x), bu1 = f2tf(uu.y);
#pragma unroll
                for (int mt = 0; mt < 4; mt++) {
                    mma_tf32(accg[mt][0], accg[mt][1], accg[mt][2], accg[mt][3],
                             a[mt][0], a[mt][1], a[mt][2], a[mt][3], bg0, bg1);
                    mma_tf32(accu[mt][0], accu[mt][1], accu[mt][2], accu[mt][3],
                             a[mt][0], a[mt][1], a[mt][2], a[mt][3], bu0, bu1);
                }
            }
        }
        __syncthreads();
    }

    // SwiGLU epilogue; store h pre-rounded tf32 (pass2 A then needs no cvt)
    float sc0 = s0[e], sc1 = s1[e];
#pragma unroll
    for (int mt = 0; mt < 4; mt++) {
#pragma unroll
        for (int half = 0; half < 2; half++) {
            int row = rm + mt * 16 + (L >> 2) + half * 8;
            int m   = m0 + row;
            if (m >= end) continue;
            int col = cn + (L & 3) * 2;
            float gv0 = accg[mt][half * 2 + 0] * sc0;
            float gv1 = accg[mt][half * 2 + 1] * sc0;
            float uv0 = accu[mt][half * 2 + 0] * sc1;
            float uv1 = accu[mt][half * 2 + 1] * sc1;
            float h0 = (gv0 / (1.f + expf(-gv0))) * uv0;
            float h1 = (gv1 / (1.f + expf(-gv1))) * uv1;
            *reinterpret_cast<float2*>(g_H + (size_t)m * DFF + n0 + col) =
                make_float2(__uint_as_float(f2tf(h0)), __uint_as_float(f2tf(h1)));
        }
    }
}

// ---------------- pass 2: Y[slot] = wt*s2 * (H @ w2^T) ----------------------
// Block 128(M) x 64(N). 8 warps = 2(M) x 4(N); warp 64x16. 32 accs -> occ 3.
// Buffer rows: A 0-127, B 128-191.
#define P2_ROWS 192
#define P2_SMEM (2*P2_ROWS*LDSW*4)

__global__ __launch_bounds__(256, 3)
void k_down(const float* __restrict__ w2,
            const float* __restrict__ s2) {
    int tile = blockIdx.x;
    if (tile >= g_ntiles) return;
    int e   = g_tile_e[tile];
    int m0  = g_tile_m0[tile];
    int end = g_off[e + 1];
    int n0  = blockIdx.y * 64;

    extern __shared__ __align__(16) float sm[];
    float (*buf)[P2_ROWS * LDSW] = (float(*)[P2_ROWS * LDSW])sm;

    int tid = threadIdx.x;
    const float* w2e = w2 + (size_t)e * DD * DFF;

    auto prefetch = [&](int s, int k0) {
        float* b = buf[s];
#pragma unroll
        for (int i = 0; i < 4; i++) {
            int lin = tid + i * 256, row = lin >> 3, c4 = (lin & 7) * 4;
            cp16(b + row * LDSW + c4, g_H + (size_t)(m0 + row) * DFF + k0 + c4);
        }
#pragma unroll
        for (int i = 0; i < 2; i++) {
            int lin = tid + i * 256, row = lin >> 3, c4 = (lin & 7) * 4;   // 64 rows
            cp16(b + (128 + row) * LDSW + c4, w2e + (size_t)(n0 + row) * DFF + k0 + c4);
        }
    };

    int w  = tid >> 5, L = tid & 31;
    int wm = w & 1, wn = w >> 1;       // 2(M) x 4(N)
    int rm = wm * 64, cn = wn * 16;
    int cw = 2 * (L & 3);

    float acc[4][2][4] = {};

    const int NT = DFF / KT;   // 32
    prefetch(0, 0);
    CP_COMMIT();

    for (int it = 0; it < NT; it++) {
        if (it + 1 < NT) prefetch((it + 1) & 1, (it + 1) * KT);
        CP_COMMIT();
        CP_WAIT1();
        __syncthreads();
        const float* bp = buf[it & 1];

#pragma unroll
        for (int kk = 0; kk < KT; kk += 8) {
            uint32_t a[4][4];
#pragma unroll
            for (int mt = 0; mt < 4; mt++) {
                int r = rm + mt * 16 + (L >> 2);
                float2 lo = *reinterpret_cast<const float2*>(bp + r * LDSW + kk + cw);
                float2 hi = *reinterpret_cast<const float2*>(bp + (r + 8) * LDSW + kk + cw);
                a[mt][0] = __float_as_uint(lo.x);
                a[mt][1] = __float_as_uint(hi.x);
                a[mt][2] = __float_as_uint(lo.y);
                a[mt][3] = __float_as_uint(hi.y);
            }
#pragma unroll
            for (int nt = 0; nt < 2; nt++) {
                int col = cn + nt * 8 + (L >> 2);
                float2 bb = *reinterpret_cast<const float2*>(bp + (128 + col) * LDSW + kk + cw);
                uint32_t b0 = f2tf(bb.x), b1 = f2tf(bb.y);
#pragma unroll
                for (int mt = 0; mt < 4; mt++)
                    mma_tf32(acc[mt][nt][0], acc[mt][nt][1], acc[mt][nt][2], acc[mt][nt][3],
                             a[mt][0], a[mt][1], a[mt][2], a[mt][3], b0, b1);
            }
        }
        __syncthreads();
    }

    float sce = s2[e];
#pragma unroll
    for (int mt = 0; mt < 4; mt++) {
#pragma unroll
        for (int half = 0; half < 2; half++) {
            int row = rm + mt * 16 + (L >> 2) + half * 8;
            int m   = m0 + row;
            if (m >= end) continue;
            int   slot = g_slot[m];
            float wv   = g_wt[m] * sce;
            float* yp  = g_Y + (size_t)slot * DD + n0;
#pragma unroll
            for (int nt = 0; nt < 2; nt++) {
                int col = cn + nt * 8 + (L & 3) * 2;
                *reinterpret_cast<float2*>(yp + col) =
                    make_float2(wv * acc[mt][nt][half * 2 + 0],
                                wv * acc[mt][nt][half * 2 + 1]);
            }
        }
    }
}

// ---------------- pass 3: out[t] = sum_k Y[t*6+k] ---------------------------
__global__ void k_reduce(float* __restrict__ out) {
    int i = blockIdx.x * blockDim.x + threadIdx.x;
    int t  = i / (DD / 4);
    int d4 = (i % (DD / 4)) * 4;
    const float* base = g_Y + (size_t)t * KSLOT * DD + d4;
    float4 acc = make_float4(0.f, 0.f, 0.f, 0.f);
#pragma unroll
    for (int k = 0; k < KSLOT; k++) {
        float4 v = *reinterpret_cast<const float4*>(base + (size_t)k * DD);
        acc.x += v.x; acc.y += v.y; acc.z += v.z; acc.w += v.w;
    }
    *reinterpret_cast<float4*>(out + (size_t)t * DD + d4) = acc;
}

// ---------------- launch ----------------------------------------------------
extern "C" void kernel_launch(void* const* d_in, const int* in_sizes, int n_in,
                              void* d_out, int out_size) {
    const float* x  = (const float*)d_in[0];
    const float* w0 = (const float*)d_in[1];
    const float* w1 = (const float*)d_in[2];
    const float* w2 = (const float*)d_in[3];
    const float* s0 = (const float*)d_in[4];
    const float* s1 = (const float*)d_in[5];
    const float* s2 = (const float*)d_in[6];
    const int*   se = (const int*)d_in[7];
    const float* rw = (const float*)d_in[8];
    float* out = (float*)d_out;

    static bool attr_set = false;
    if (!attr_set) {
        cudaFuncSetAttribute(k_gateup, cudaFuncAttributeMaxDynamicSharedMemorySize, P1_SMEM);
        cudaFuncSetAttribute(k_down,   cudaFuncAttributeMaxDynamicSharedMemorySize, P2_SMEM);
        attr_set = true;
    }

    k_prep<<<(TT * DD / 4) / 256, 256>>>(x);
    k_route<<<1, 1024>>>(se, rw);

    dim3 g1(MAXTILES, DFF / 32);
    k_gateup<<<g1, 256, P1_SMEM>>>(w0, w1, s0, s1);

    dim3 g2(MAXTILES, DD / 64);
    k_down<<<g2, 256, P2_SMEM>>>(w2, s2);

    k_reduce<<<(TT * DD / 4) / 256, 256>>>(out);
}

// round 13
// speedup vs baseline: 1.3084x; 1.3084x over previous
#include <cuda_runtime.h>
#include <math.h>
#include <stdint.h>

#define TT    1024
#define DD    2048
#define DFF   1024
#define EE    16
#define KSLOT 6
#define TK    (TT*KSLOT)
#define MAXTILES 64
#define KT    32
#define LDSW  40          // B-region row stride (words), conflict-free
#define TILE_FLOATS (8*128*128)   // fragment-layout floats per 128x1024 tile slice

// ---------------- scratch (device globals; no allocations allowed) ----------
__device__ int   g_off[EE + 1];
__device__ int   g_tok[TK];
__device__ int   g_slot[TK];
__device__ float g_wt[TK];
__device__ int   g_tile_e[MAXTILES];
__device__ int   g_tile_m0[MAXTILES];
__device__ int   g_ntiles;
// fragment-unit layouts: [tile][a(8)][g(128)][unit(32) of 16B]
__device__ __align__(16) float g_XG[(size_t)MAXTILES * 8 * 128 * 128 * 2]; // 2048 cols -> g<256
__device__ __align__(16) float g_H [(size_t)MAXTILES * TILE_FLOATS];       // 1024 cols -> g<128
__device__ __align__(16) float g_Y [(size_t)TK * DD];

// ---------------- helpers ----------------------------------------------------
__device__ __forceinline__ uint32_t f2tf(float f) {
    uint32_t u;
    asm("cvt.rna.tf32.f32 %0, %1;" : "=r"(u) : "f"(f));
    return u;
}

__device__ __forceinline__ void mma_tf32(float& d0, float& d1, float& d2, float& d3,
                                         uint32_t a0, uint32_t a1, uint32_t a2, uint32_t a3,
                                         uint32_t b0, uint32_t b1) {
    asm volatile(
        "mma.sync.aligned.m16n8k8.row.col.f32.tf32.tf32.f32 "
        "{%0,%1,%2,%3},{%4,%5,%6,%7},{%8,%9},{%0,%1,%2,%3};"
        : "+f"(d0), "+f"(d1), "+f"(d2), "+f"(d3)
        : "r"(a0), "r"(a1), "r"(a2), "r"(a3), "r"(b0), "r"(b1));
}

__device__ __forceinline__ void cp16(void* smem_dst, const void* gmem_src) {
    unsigned d = (unsigned)__cvta_generic_to_shared(smem_dst);
    asm volatile("cp.async.cg.shared.global [%0], [%1], 16;" :: "r"(d), "l"(gmem_src));
}
#define CP_COMMIT() asm volatile("cp.async.commit_group;")
#define CP_WAIT1()  asm volatile("cp.async.wait_group 1;")

// ---------------- routing: one CTA does count+scan+scatter ------------------
__global__ void k_route(const int* __restrict__ se, const float* __restrict__ rw) {
    __shared__ int cnt[EE], cur[EE], off[EE + 1];
    int tid = threadIdx.x;
    if (tid < EE) { cnt[tid] = 0; cur[tid] = 0; }
    __syncthreads();
    for (int i = tid; i < TK; i += 1024) atomicAdd(&cnt[se[i] & (EE - 1)], 1);
    __syncthreads();
    if (tid == 0) {
        int s = 0, nt = 0;
        off[0] = 0; g_off[0] = 0;
        for (int e = 0; e < EE; e++) {
            int o = s;
            s += cnt[e];
            off[e + 1] = s; g_off[e + 1] = s;
            for (int m0 = o; m0 < s; m0 += 128) {
                g_tile_e[nt] = e; g_tile_m0[nt] = m0; nt++;
            }
        }
        g_ntiles = nt;
    }
    __syncthreads();
    for (int i = tid; i < TK; i += 1024) {
        int e = se[i] & (EE - 1);
        int p = off[e] + atomicAdd(&cur[e], 1);
        g_tok[p]  = i / KSLOT;
        g_slot[p] = i;
        g_wt[p]   = rw[i];
    }
}

// ---------------- gather: g_XG = fragment-packed, tf32-rounded, token-gathered x
// unit (tile,a,g,rr,q) = [x(r0,c0), x(r1,c0), x(r0,c1), x(r1,c1)],
// r0=16a+rr, r1=r0+8 (tile-relative), c0=8g+2q.
__global__ void k_gather(const float* __restrict__ x) {
    int t = blockIdx.x;
    if (t >= g_ntiles) return;
    int gb = blockIdx.y * 16;            // 16 g-groups per block (128 cols)
    __shared__ int toks[128];
    int tid = threadIdx.x;
    int m0  = g_tile_m0[t];
    int end = g_off[g_tile_e[t] + 1];
    if (tid < 128) {
        int m = m0 + tid;
        toks[tid] = (m < end) ? g_tok[m] : 0;
    }
    __syncthreads();
    float* dstT = g_XG + (size_t)t * (8 * 128 * 128 * 2);
#pragma unroll
    for (int i = 0; i < 16; i++) {
        int u  = tid + i * 256;          // 4096 units
        int a  = u >> 9;
        int gl = (u >> 5) & 15;
        int rr = (u >> 2) & 7;
        int q  = u & 3;
        int g  = gb + gl;
        int r0 = a * 16 + rr;
        float2 v0 = *reinterpret_cast<const float2*>(x + (size_t)toks[r0] * DD + g * 8 + q * 2);
        float2 v1 = *reinterpret_cast<const float2*>(x + (size_t)toks[r0 + 8] * DD + g * 8 + q * 2);
        *reinterpret_cast<uint4*>(dstT + ((size_t)a * 256 + g) * 128 + (rr * 4 + q) * 4) =
            make_uint4(f2tf(v0.x), f2tf(v1.x), f2tf(v0.y), f2tf(v1.y));
    }
}

// ---------------- pass 1: H = silu(x@w0^T*s0) * (x@w1^T*s1) -----------------
// 128(M) x 64(N dff) tile; 8 warps = 2(M) x 4(N); warp 64x16 per matrix.
// A: fragment units via cp.async + LDS.128. B: rows + consumer cvt (as R9).
// Stage layout (floats): A[0..4096), Bg[4096..+64*LDSW), Bu after.
#define P1_STAGE (4096 + 128*LDSW)
#define P1_SMEM  (2*P1_STAGE*4)

__global__ __launch_bounds__(256, 2)
void k_gateup(const float* __restrict__ w0,
              const float* __restrict__ w1,
              const float* __restrict__ s0,
              const float* __restrict__ s1) {
    int tile = blockIdx.x;
    if (tile >= g_ntiles) return;
    int e   = g_tile_e[tile];
    int n0  = blockIdx.y * 64;

    extern __shared__ __align__(16) float sm[];
    int tid = threadIdx.x;

    const float* w0e = w0 + (size_t)e * DFF * DD;
    const float* w1e = w1 + (size_t)e * DFF * DD;
    const float* xgT = g_XG + (size_t)tile * (8 * 128 * 128 * 2);

    auto prefetch = [&](int s, int k0) {
        float* bs = sm + s * P1_STAGE;
        int kg0 = k0 >> 3;
#pragma unroll
        for (int i = 0; i < 4; i++) {
            int lin = tid + i * 256;                 // 1024 units
            int a = lin >> 7, gg = (lin >> 5) & 3, unit = lin & 31;
            cp16(bs + lin * 4, xgT + ((size_t)a * 256 + kg0 + gg) * 128 + unit * 4);
        }
#pragma unroll
        for (int i = 0; i < 2; i++) {
            int lin = tid + i * 256;
            int row = lin >> 3, c4 = (lin & 7) * 4;
            size_t boff = (size_t)(n0 + row) * DD + k0 + c4;
            cp16(bs + 4096 + row * LDSW + c4, w0e + boff);
            cp16(bs + 4096 + 64 * LDSW + row * LDSW + c4, w1e + boff);
        }
    };

    int w  = tid >> 5, L = tid & 31;
    int wm = w & 1, wn = w >> 1;       // 2(M) x 4(N)
    int cn = wn * 16;
    int cw = 2 * (L & 3);

    float accg[4][2][4] = {}, accu[4][2][4] = {};

    const int NT = DD / KT;   // 64
    prefetch(0, 0);
    CP_COMMIT();

    for (int it = 0; it < NT; it++) {
        if (it + 1 < NT) prefetch((it + 1) & 1, (it + 1) * KT);
        CP_COMMIT();
        CP_WAIT1();
        __syncthreads();
        const float* bs = sm + (it & 1) * P1_STAGE;

#pragma unroll
        for (int gg = 0; gg < 4; gg++) {
            int kk = gg * 8;
            uint32_t a[4][4];
#pragma unroll
            for (int mt = 0; mt < 4; mt++) {
                int aa = wm * 4 + mt;
                float4 f = *reinterpret_cast<const float4*>(bs + ((aa * 4 + gg) * 32 + L) * 4);
                a[mt][0] = __float_as_uint(f.x);
                a[mt][1] = __float_as_uint(f.y);
                a[mt][2] = __float_as_uint(f.z);
                a[mt][3] = __float_as_uint(f.w);
            }
#pragma unroll
            for (int nt = 0; nt < 2; nt++) {
                int col = cn + nt * 8 + (L >> 2);
                float2 gg2 = *reinterpret_cast<const float2*>(bs + 4096 + col * LDSW + kk + cw);
                float2 uu2 = *reinterpret_cast<const float2*>(bs + 4096 + 64 * LDSW + col * LDSW + kk + cw);
                uint32_t bg0 = f2tf(gg2.x), bg1 = f2tf(gg2.y);
                uint32_t bu0 = f2tf(uu2.x), bu1 = f2tf(uu2.y);
#pragma unroll
                for (int mt = 0; mt < 4; mt++) {
                    mma_tf32(accg[mt][nt][0], accg[mt][nt][1], accg[mt][nt][2], accg[mt][nt][3],
                             a[mt][0], a[mt][1], a[mt][2], a[mt][3], bg0, bg1);
                    mma_tf32(accu[mt][nt][0], accu[mt][nt][1], accu[mt][nt][2], accu[mt][nt][3],
                             a[mt][0], a[mt][1], a[mt][2], a[mt][3], bu0, bu1);
                }
            }
        }
        __syncthreads();
    }

    // SwiGLU epilogue -> g_H fragment units, STG.128 per (mt,nt).
    // acc idx = half*2+p; unit order = [h00, h10, h01, h11].
    float sc0 = s0[e], sc1 = s1[e];
    float* hT = g_H + (size_t)tile * TILE_FLOATS;
#pragma unroll
    for (int mt = 0; mt < 4; mt++) {
        int aa = wm * 4 + mt;
#pragma unroll
        for (int nt = 0; nt < 2; nt++) {
            int g = (n0 >> 3) + wn * 2 + nt;
            float h[4];
#pragma unroll
            for (int idx = 0; idx < 4; idx++) {
                float gv = accg[mt][nt][idx] * sc0;
                float uv = accu[mt][nt][idx] * sc1;
                h[idx] = (gv / (1.f + expf(-gv))) * uv;
            }
            *reinterpret_cast<uint4*>(hT + ((size_t)aa * 128 + g) * 128 + ((L >> 2) * 4 + (L & 3)) * 4) =
                make_uint4(f2tf(h[0]), f2tf(h[2]), f2tf(h[1]), f2tf(h[3]));
        }
    }
}

// ---------------- pass 2: Y[slot] = wt*s2 * (H @ w2^T) ----------------------
// 128x128 tile; 8 warps = 2(M) x 4(N); warp 64x32.
// A: fragment units from g_H (LDS.128, no cvt). B: rows + consumer cvt.
#define P2_STAGE (4096 + 128*LDSW)
#define P2_SMEM  (2*P2_STAGE*4)

__global__ __launch_bounds__(256, 2)
void k_down(const float* __restrict__ w2,
            const float* __restrict__ s2) {
    int tile = blockIdx.x;
    if (tile >= g_ntiles) return;
    int e   = g_tile_e[tile];
    int m0  = g_tile_m0[tile];
    int end = g_off[e + 1];
    int n0  = blockIdx.y * 128;

    extern __shared__ __align__(16) float sm[];
    int tid = threadIdx.x;

    const float* w2e = w2 + (size_t)e * DD * DFF;
    const float* hT  = g_H + (size_t)tile * TILE_FLOATS;

    auto prefetch = [&](int s, int k0) {
        float* bs = sm + s * P2_STAGE;
        int kg0 = k0 >> 3;
#pragma unroll
        for (int i = 0; i < 4; i++) {
            int lin = tid + i * 256;
            int a = lin >> 7, gg = (lin >> 5) & 3, unit = lin & 31;
            cp16(bs + lin * 4, hT + ((size_t)a * 128 + kg0 + gg) * 128 + unit * 4);
        }
#pragma unroll
        for (int i = 0; i < 4; i++) {
            int lin = tid + i * 256;
            int row = lin >> 3, c4 = (lin & 7) * 4;
            cp16(bs + 4096 + row * LDSW + c4, w2e + (size_t)(n0 + row) * DFF + k0 + c4);
        }
    };

    int w  = tid >> 5, L = tid & 31;
    int wm = w & 1, wn = w >> 1;       // 2(M) x 4(N)
    int rm = wm * 64, cn = wn * 32;
    int cw = 2 * (L & 3);

    float acc[4][4][4] = {};

    const int NT = DFF / KT;   // 32
    prefetch(0, 0);
    CP_COMMIT();

    for (int it = 0; it < NT; it++) {
        if (it + 1 < NT) prefetch((it + 1) & 1, (it + 1) * KT);
        CP_COMMIT();
        CP_WAIT1();
        __syncthreads();
        const float* bs = sm + (it & 1) * P2_STAGE;

#pragma unroll
        for (int gg = 0; gg < 4; gg++) {
            int kk = gg * 8;
            uint32_t a[4][4];
#pragma unroll
            for (int mt = 0; mt < 4; mt++) {
                int aa = wm * 4 + mt;
                float4 f = *reinterpret_cast<const float4*>(bs + ((aa * 4 + gg) * 32 + L) * 4);
                a[mt][0] = __float_as_uint(f.x);
                a[mt][1] = __float_as_uint(f.y);
                a[mt][2] = __float_as_uint(f.z);
                a[mt][3] = __float_as_uint(f.w);
            }
#pragma unroll
            for (int nt = 0; nt < 4; nt++) {
                int col = cn + nt * 8 + (L >> 2);
                float2 bb = *reinterpret_cast<const float2*>(bs + 4096 + col * LDSW + kk + cw);
                uint32_t b0 = f2tf(bb.x), b1 = f2tf(bb.y);
#pragma unroll
                for (int mt = 0; mt < 4; mt++)
                    mma_tf32(acc[mt][nt][0], acc[mt][nt][1], acc[mt][nt][2], acc[mt][nt][3],
                             a[mt][0], a[mt][1], a[mt][2], a[mt][3], b0, b1);
            }
        }
        __syncthreads();
    }

    float sce = s2[e];
#pragma unroll
    for (int mt = 0; mt < 4; mt++) {
#pragma unroll
        for (int half = 0; half < 2; half++) {
            int row = rm + mt * 16 + (L >> 2) + half * 8;
            int m   = m0 + row;
            if (m >= end) continue;
            int   slot = g_slot[m];
            float wv   = g_wt[m] * sce;
            float* yp  = g_Y + (size_t)slot * DD + n0;
#pragma unroll
            for (int nt = 0; nt < 4; nt++) {
                int col = cn + nt * 8 + (L & 3) * 2;
                *reinterpret_cast<float2*>(yp + col) =
                    make_float2(wv * acc[mt][nt][half * 2 + 0],
                                wv * acc[mt][nt][half * 2 + 1]);
            }
        }
    }
}

// ---------------- pass 3: out[t] = sum_k Y[t*6+k] ---------------------------
__global__ void k_reduce(float* __restrict__ out) {
    int i = blockIdx.x * blockDim.x + threadIdx.x;
    int t  = i / (DD / 4);
    int d4 = (i % (DD / 4)) * 4;
    const float* base = g_Y + (size_t)t * KSLOT * DD + d4;
    float4 acc = make_float4(0.f, 0.f, 0.f, 0.f);
#pragma unroll
    for (int k = 0; k < KSLOT; k++) {
        float4 v = *reinterpret_cast<const float4*>(base + (size_t)k * DD);
        acc.x += v.x; acc.y += v.y; acc.z += v.z; acc.w += v.w;
    }
    *reinterpret_cast<float4*>(out + (size_t)t * DD + d4) = acc;
}

// ---------------- launch ----------------------------------------------------
extern "C" void kernel_launch(void* const* d_in, const int* in_sizes, int n_in,
                              void* d_out, int out_size) {
    const float* x  = (const float*)d_in[0];
    const float* w0 = (const float*)d_in[1];
    const float* w1 = (const float*)d_in[2];
    const float* w2 = (const float*)d_in[3];
    const float* s0 = (const float*)d_in[4];
    const float* s1 = (const float*)d_in[5];
    const float* s2 = (const float*)d_in[6];
    const int*   se = (const int*)d_in[7];
    const float* rw = (const float*)d_in[8];
    float* out = (float*)d_out;

    static bool attr_set = false;
    if (!attr_set) {
        cudaFuncSetAttribute(k_gateup, cudaFuncAttributeMaxDynamicSharedMemorySize, P1_SMEM);
        cudaFuncSetAttribute(k_down,   cudaFuncAttributeMaxDynamicSharedMemorySize, P2_SMEM);
        attr_set = true;
    }

    k_route<<<1, 1024>>>(se, rw);

    dim3 gg(MAXTILES, DD / 128);           // 16 col-chunks of 128
    k_gather<<<gg, 256>>>(x);

    dim3 g1(MAXTILES, DFF / 64);
    k_gateup<<<g1, 256, P1_SMEM>>>(w0, w1, s0, s1);

    dim3 g2(MAXTILES, DD / 128);
    k_down<<<g2, 256, P2_SMEM>>>(w2, s2);

    k_reduce<<<(TT * DD / 4) / 256, 256>>>(out);
}

// round 15
// speedup vs baseline: 1.3311x; 1.0173x over previous
#include <cuda_runtime.h>
#include <math.h>
#include <stdint.h>

#define TT    1024
#define DD    2048
#define DFF   1024
#define EE    16
#define KSLOT 6
#define TK    (TT*KSLOT)
#define MAXTILES 64
#define KT    32
#define LDSW  40          // B-region row stride (words), conflict-free
#define TILE_FLOATS (8*128*128)   // fragment-layout floats per 128x1024 tile slice

// ---------------- scratch (device globals; no allocations allowed) ----------
__device__ int   g_off[EE + 1];
__device__ int   g_tok[TK];
__device__ int   g_slot[TK];
__device__ float g_wt[TK];
__device__ int   g_tile_e[MAXTILES];
__device__ int   g_tile_m0[MAXTILES];
__device__ int   g_ntiles;
// fragment-unit layouts: [tile][a(8)][g][unit(32) of 16B]
__device__ __align__(16) float g_XG[(size_t)MAXTILES * 8 * 128 * 128 * 2];
__device__ __align__(16) float g_H [(size_t)MAXTILES * TILE_FLOATS];
__device__ __align__(16) float g_Y [(size_t)TK * DD];

// ---------------- helpers ----------------------------------------------------
__device__ __forceinline__ uint32_t f2tf(float f) {
    uint32_t u;
    asm("cvt.rna.tf32.f32 %0, %1;" : "=r"(u) : "f"(f));
    return u;
}

__device__ __forceinline__ void mma_tf32(float& d0, float& d1, float& d2, float& d3,
                                         uint32_t a0, uint32_t a1, uint32_t a2, uint32_t a3,
                                         uint32_t b0, uint32_t b1) {
    asm volatile(
        "mma.sync.aligned.m16n8k8.row.col.f32.tf32.tf32.f32 "
        "{%0,%1,%2,%3},{%4,%5,%6,%7},{%8,%9},{%0,%1,%2,%3};"
        : "+f"(d0), "+f"(d1), "+f"(d2), "+f"(d3)
        : "r"(a0), "r"(a1), "r"(a2), "r"(a3), "r"(b0), "r"(b1));
}

__device__ __forceinline__ void cp16(void* smem_dst, const void* gmem_src) {
    unsigned d = (unsigned)__cvta_generic_to_shared(smem_dst);
    asm volatile("cp.async.cg.shared.global [%0], [%1], 16;" :: "r"(d), "l"(gmem_src));
}
#define CP_COMMIT() asm volatile("cp.async.commit_group;")
#define CP_WAIT1()  asm volatile("cp.async.wait_group 1;")

// ---------------- routing: one CTA does count+scan+scatter ------------------
__global__ void k_route(const int* __restrict__ se, const float* __restrict__ rw) {
    __shared__ int cnt[EE], cur[EE], off[EE + 1];
    int tid = threadIdx.x;
    if (tid < EE) { cnt[tid] = 0; cur[tid] = 0; }
    __syncthreads();
    for (int i = tid; i < TK; i += 1024) atomicAdd(&cnt[se[i] & (EE - 1)], 1);
    __syncthreads();
    if (tid == 0) {
        int s = 0, nt = 0;
        off[0] = 0; g_off[0] = 0;
        for (int e = 0; e < EE; e++) {
            int o = s;
            s += cnt[e];
            off[e + 1] = s; g_off[e + 1] = s;
            for (int m0 = o; m0 < s; m0 += 128) {
                g_tile_e[nt] = e; g_tile_m0[nt] = m0; nt++;
            }
        }
        g_ntiles = nt;
    }
    __syncthreads();
    for (int i = tid; i < TK; i += 1024) {
        int e = se[i] & (EE - 1);
        int p = off[e] + atomicAdd(&cur[e], 1);
        g_tok[p]  = i / KSLOT;
        g_slot[p] = i;
        g_wt[p]   = rw[i];
    }
}

// ---------------- gather: g_XG = fragment-packed, tf32-rounded, gathered x --
__global__ void k_gather(const float* __restrict__ x) {
    int t = blockIdx.x;
    if (t >= g_ntiles) return;
    int gb = blockIdx.y * 16;            // 16 g-groups per block (128 cols)
    __shared__ int toks[128];
    int tid = threadIdx.x;
    int m0  = g_tile_m0[t];
    int end = g_off[g_tile_e[t] + 1];
    if (tid < 128) {
        int m = m0 + tid;
        toks[tid] = (m < end) ? g_tok[m] : 0;
    }
    __syncthreads();
    float* dstT = g_XG + (size_t)t * (8 * 128 * 128 * 2);
#pragma unroll
    for (int i = 0; i < 16; i++) {
        int u  = tid + i * 256;          // 4096 units
        int a  = u >> 9;
        int gl = (u >> 5) & 15;
        int rr = (u >> 2) & 7;
        int q  = u & 3;
        int g  = gb + gl;
        int r0 = a * 16 + rr;
        float2 v0 = *reinterpret_cast<const float2*>(x + (size_t)toks[r0] * DD + g * 8 + q * 2);
        float2 v1 = *reinterpret_cast<const float2*>(x + (size_t)toks[r0 + 8] * DD + g * 8 + q * 2);
        *reinterpret_cast<uint4*>(dstT + ((size_t)a * 256 + g) * 128 + (rr * 4 + q) * 4) =
            make_uint4(f2tf(v0.x), f2tf(v1.x), f2tf(v0.y), f2tf(v1.y));
    }
}

// ---------------- pass 1: H = silu(x@w0^T*s0) * (x@w1^T*s1) -----------------
// 128(M) x 64(N dff) tile; 8 warps = 2(M) x 4(N). 3-stage pipeline, 1 bar/iter.
#define P1_STAGE (4096 + 128*LDSW)
#define P1_SMEM  (3*P1_STAGE*4)

__global__ __launch_bounds__(256, 2)
void k_gateup(const float* __restrict__ w0,
              const float* __restrict__ w1,
              const float* __restrict__ s0,
              const float* __restrict__ s1) {
    int tile = blockIdx.x;
    if (tile >= g_ntiles) return;
    int e   = g_tile_e[tile];
    int n0  = blockIdx.y * 64;

    extern __shared__ __align__(16) float sm[];
    int tid = threadIdx.x;

    const float* w0e = w0 + (size_t)e * DFF * DD;
    const float* w1e = w1 + (size_t)e * DFF * DD;
    const float* xgT = g_XG + (size_t)tile * (8 * 128 * 128 * 2);

    auto prefetch = [&](int s, int k0) {
        float* bs = sm + s * P1_STAGE;
        int kg0 = k0 >> 3;
#pragma unroll
        for (int i = 0; i < 4; i++) {
            int lin = tid + i * 256;                 // 1024 units
            int a = lin >> 7, gg = (lin >> 5) & 3, unit = lin & 31;
            cp16(bs + lin * 4, xgT + ((size_t)a * 256 + kg0 + gg) * 128 + unit * 4);
        }
#pragma unroll
        for (int i = 0; i < 2; i++) {
            int lin = tid + i * 256;
            int row = lin >> 3, c4 = (lin & 7) * 4;
            size_t boff = (size_t)(n0 + row) * DD + k0 + c4;
            cp16(bs + 4096 + row * LDSW + c4, w0e + boff);
            cp16(bs + 4096 + 64 * LDSW + row * LDSW + c4, w1e + boff);
        }
    };

    int w  = tid >> 5, L = tid & 31;
    int wm = w & 1, wn = w >> 1;       // 2(M) x 4(N)
    int cn = wn * 16;
    int cw = 2 * (L & 3);

    float accg[4][2][4] = {}, accu[4][2][4] = {};

    const int NT = DD / KT;   // 64
    prefetch(0, 0);       CP_COMMIT();
    prefetch(1, KT);      CP_COMMIT();

    int stage = 0;
    for (int it = 0; it < NT; it++) {
        CP_WAIT1();
        __syncthreads();
        int ps = stage + 2; if (ps >= 3) ps -= 3;
        if (it + 2 < NT) prefetch(ps, (it + 2) * KT);
        CP_COMMIT();
        const float* bs = sm + stage * P1_STAGE;

#pragma unroll
        for (int gg = 0; gg < 4; gg++) {
            int kk = gg * 8;
            uint32_t a[4][4];
#pragma unroll
            for (int mt = 0; mt < 4; mt++) {
                int aa = wm * 4 + mt;
                float4 f = *reinterpret_cast<const float4*>(bs + ((aa * 4 + gg) * 32 + L) * 4);
                a[mt][0] = __float_as_uint(f.x);
                a[mt][1] = __float_as_uint(f.y);
                a[mt][2] = __float_as_uint(f.z);
                a[mt][3] = __float_as_uint(f.w);
            }
#pragma unroll
            for (int nt = 0; nt < 2; nt++) {
                int col = cn + nt * 8 + (L >> 2);
                float2 gg2 = *reinterpret_cast<const float2*>(bs + 4096 + col * LDSW + kk + cw);
                float2 uu2 = *reinterpret_cast<const float2*>(bs + 4096 + 64 * LDSW + col * LDSW + kk + cw);
                uint32_t bg0 = f2tf(gg2.x), bg1 = f2tf(gg2.y);
                uint32_t bu0 = f2tf(uu2.x), bu1 = f2tf(uu2.y);
#pragma unroll
                for (int mt = 0; mt < 4; mt++) {
                    mma_tf32(accg[mt][nt][0], accg[mt][nt][1], accg[mt][nt][2], accg[mt][nt][3],
                             a[mt][0], a[mt][1], a[mt][2], a[mt][3], bg0, bg1);
                    mma_tf32(accu[mt][nt][0], accu[mt][nt][1], accu[mt][nt][2], accu[mt][nt][3],
                             a[mt][0], a[mt][1], a[mt][2], a[mt][3], bu0, bu1);
                }
            }
        }
        if (++stage == 3) stage = 0;
    }

    // SwiGLU epilogue -> g_H fragment units, STG.128 per (mt,nt).
    float sc0 = s0[e], sc1 = s1[e];
    float* hT = g_H + (size_t)tile * TILE_FLOATS;
#pragma unroll
    for (int mt = 0; mt < 4; mt++) {
        int aa = wm * 4 + mt;
#pragma unroll
        for (int nt = 0; nt < 2; nt++) {
            int g = (n0 >> 3) + wn * 2 + nt;
            float h[4];
#pragma unroll
            for (int idx = 0; idx < 4; idx++) {
                float gv = accg[mt][nt][idx] * sc0;
                float uv = accu[mt][nt][idx] * sc1;
                h[idx] = (gv / (1.f + expf(-gv))) * uv;
            }
            *reinterpret_cast<uint4*>(hT + ((size_t)aa * 128 + g) * 128 + ((L >> 2) * 4 + (L & 3)) * 4) =
                make_uint4(f2tf(h[0]), f2tf(h[2]), f2tf(h[1]), f2tf(h[3]));
        }
    }
}

// ---------------- pass 2: Y[slot] = wt*s2 * (H @ w2^T) ----------------------
// 128x128 tile; 8 warps = 2(M) x 4(N). 3-stage pipeline, 1 bar/iter.
#define P2_STAGE (4096 + 128*LDSW)
#define P2_SMEM  (3*P2_STAGE*4)

__global__ __launch_bounds__(256, 2)
void k_down(const float* __restrict__ w2,
            const float* __restrict__ s2) {
    int tile = blockIdx.x;
    if (tile >= g_ntiles) return;
    int e   = g_tile_e[tile];
    int m0  = g_tile_m0[tile];
    int end = g_off[e + 1];
    int n0  = blockIdx.y * 128;

    extern __shared__ __align__(16) float sm[];
    int tid = threadIdx.x;

    const float* w2e = w2 + (size_t)e * DD * DFF;
    const float* hT  = g_H + (size_t)tile * TILE_FLOATS;

    auto prefetch = [&](int s, int k0) {
        float* bs = sm + s * P2_STAGE;
        int kg0 = k0 >> 3;
#pragma unroll
        for (int i = 0; i < 4; i++) {
            int lin = tid + i * 256;
            int a = lin >> 7, gg = (lin >> 5) & 3, unit = lin & 31;
            cp16(bs + lin * 4, hT + ((size_t)a * 128 + kg0 + gg) * 128 + unit * 4);
        }
#pragma unroll
        for (int i = 0; i < 4; i++) {
            int lin = tid + i * 256;
            int row = lin >> 3, c4 = (lin & 7) * 4;
            cp16(bs + 4096 + row * LDSW + c4, w2e + (size_t)(n0 + row) * DFF + k0 + c4);
        }
    };

    int w  = tid >> 5, L = tid & 31;
    int wm = w & 1, wn = w >> 1;       // 2(M) x 4(N)
    int rm = wm * 64, cn = wn * 32;
    int cw = 2 * (L & 3);

    float acc[4][4][4] = {};

    const int NT = DFF / KT;   // 32
    prefetch(0, 0);       CP_COMMIT();
    prefetch(1, KT);      CP_COMMIT();

    int stage = 0;
    for (int it = 0; it < NT; it++) {
        CP_WAIT1();
        __syncthreads();
        int ps = stage + 2; if (ps >= 3) ps -= 3;
        if (it + 2 < NT) prefetch(ps, (it + 2) * KT);
        CP_COMMIT();
        const float* bs = sm + stage * P2_STAGE;

#pragma unroll
        for (int gg = 0; gg < 4; gg++) {
            int kk = gg * 8;
            uint32_t a[4][4];
#pragma unroll
            for (int mt = 0; mt < 4; mt++) {
                int aa = wm * 4 + mt;
                float4 f = *reinterpret_cast<const float4*>(bs + ((aa * 4 + gg) * 32 + L) * 4);
                a[mt][0] = __float_as_uint(f.x);
                a[mt][1] = __float_as_uint(f.y);
                a[mt][2] = __float_as_uint(f.z);
                a[mt][3] = __float_as_uint(f.w);
            }
#pragma unroll
            for (int nt = 0; nt < 4; nt++) {
                int col = cn + nt * 8 + (L >> 2);
                float2 bb = *reinterpret_cast<const float2*>(bs + 4096 + col * LDSW + kk + cw);
                uint32_t b0 = f2tf(bb.x), b1 = f2tf(bb.y);
#pragma unroll
                for (int mt = 0; mt < 4; mt++)
                    mma_tf32(acc[mt][nt][0], acc[mt][nt][1], acc[mt][nt][2], acc[mt][nt][3],
                             a[mt][0], a[mt][1], a[mt][2], a[mt][3], b0, b1);
            }
        }
        if (++stage == 3) stage = 0;
    }

    float sce = s2[e];
#pragma unroll
    for (int mt = 0; mt < 4; mt++) {
#pragma unroll
        for (int half = 0; half < 2; half++) {
            int row = rm + mt * 16 + (L >> 2) + half * 8;
            int m   = m0 + row;
            if (m >= end) continue;
            int   slot = g_slot[m];
            float wv   = g_wt[m] * sce;
            float* yp  = g_Y + (size_t)slot * DD + n0;
#pragma unroll
            for (int nt = 0; nt < 4; nt++) {
                int col = cn + nt * 8 + (L & 3) * 2;
                *reinterpret_cast<float2*>(yp + col) =
                    make_float2(wv * acc[mt][nt][half * 2 + 0],
                                wv * acc[mt][nt][half * 2 + 1]);
            }
        }
    }
}

// ---------------- pass 3: out[t] = sum_k Y[t*6+k] ---------------------------
__global__ void k_reduce(float* __restrict__ out) {
    int i = blockIdx.x * blockDim.x + threadIdx.x;
    int t  = i / (DD / 4);
    int d4 = (i % (DD / 4)) * 4;
    const float* base = g_Y + (size_t)t * KSLOT * DD + d4;
    float4 acc = make_float4(0.f, 0.f, 0.f, 0.f);
#pragma unroll
    for (int k = 0; k < KSLOT; k++) {
        float4 v = *reinterpret_cast<const float4*>(base + (size_t)k * DD);
        acc.x += v.x; acc.y += v.y; acc.z += v.z; acc.w += v.w;
    }
    *reinterpret_cast<float4*>(out + (size_t)t * DD + d4) = acc;
}

// ---------------- launch ----------------------------------------------------
extern "C" void kernel_launch(void* const* d_in, const int* in_sizes, int n_in,
                              void* d_out, int out_size) {
    const float* x  = (const float*)d_in[0];
    const float* w0 = (const float*)d_in[1];
    const float* w1 = (const float*)d_in[2];
    const float* w2 = (const float*)d_in[3];
    const float* s0 = (const float*)d_in[4];
    const float* s1 = (const float*)d_in[5];
    const float* s2 = (const float*)d_in[6];
    const int*   se = (const int*)d_in[7];
    const float* rw = (const float*)d_in[8];
    float* out = (float*)d_out;

    static bool attr_set = false;
    if (!attr_set) {
        cudaFuncSetAttribute(k_gateup, cudaFuncAttributeMaxDynamicSharedMemorySize, P1_SMEM);
        cudaFuncSetAttribute(k_down,   cudaFuncAttributeMaxDynamicSharedMemorySize, P2_SMEM);
        attr_set = true;
    }

    k_route<<<1, 1024>>>(se, rw);

    dim3 gg(MAXTILES, DD / 128);
    k_gather<<<gg, 256>>>(x);

    dim3 g1(MAXTILES, DFF / 64);
    k_gateup<<<g1, 256, P1_SMEM>>>(w0, w1, s0, s1);

    dim3 g2(MAXTILES, DD / 128);
    k_down<<<g2, 256, P2_SMEM>>>(w2, s2);

    k_reduce<<<(TT * DD / 4) / 256, 256>>>(out);
}